// round 2
// baseline (speedup 1.0000x reference)
#include <cuda_runtime.h>

// Scratch: encoded (order-preserving uint) per-edge scores + global min.
#define MAX_E 600000
__device__ unsigned g_score_enc[MAX_E];
__device__ unsigned g_min_bits;

// Monotone float->uint encoding: a < b (float) <=> enc(a) < enc(b) (uint).
__device__ __forceinline__ unsigned enc_f32(float f) {
    unsigned b = __float_as_uint(f);
    return (b & 0x80000000u) ? ~b : (b | 0x80000000u);
}

__global__ void init_kernel() {
    g_min_bits = 0xFFFFFFFFu;
}

// One warp per edge (grid-stride). Each lane loads one float4 of each of the
// two gathered 128-float rows -> per-thread partial dot -> butterfly reduce.
__global__ void score_kernel(const float* __restrict__ h,
                             const int* __restrict__ src,
                             const int* __restrict__ dst,
                             int E) {
    const int lane   = threadIdx.x & 31;
    const int warp   = (int)((blockIdx.x * blockDim.x + threadIdx.x) >> 5);
    const int nwarps = (int)((gridDim.x * blockDim.x) >> 5);

    const float4* __restrict__ h4 = reinterpret_cast<const float4*>(h);

    unsigned local_min = 0xFFFFFFFFu;

    for (int e = warp; e < E; e += nwarps) {
        long long s = src[e];   // int32 index, widened for addressing
        long long d = dst[e];
        float4 a = h4[s * 32 + lane];
        float4 b = h4[d * 32 + lane];
        float acc = a.x * b.x + a.y * b.y + a.z * b.z + a.w * b.w;
        #pragma unroll
        for (int off = 16; off; off >>= 1)
            acc += __shfl_xor_sync(0xFFFFFFFFu, acc, off);
        // After full butterfly all lanes hold the complete sum.
        unsigned ebits = enc_f32(acc);
        if (lane == 0 && e < MAX_E) g_score_enc[e] = ebits;
        local_min = min(local_min, ebits);
    }

    // Block-level min, one atomic per block.
    __shared__ unsigned smin[32];
    const int wid = threadIdx.x >> 5;
    if (lane == 0) smin[wid] = local_min;
    __syncthreads();
    if (threadIdx.x == 0) {
        unsigned m = smin[0];
        const int nw = blockDim.x >> 5;
        for (int i = 1; i < nw; i++) m = min(m, smin[i]);
        atomicMin(&g_min_bits, m);
    }
}

__global__ void finalize_kernel(float* __restrict__ out, int E) {
    const int i = blockIdx.x * blockDim.x + threadIdx.x;
    if (i < E) {
        out[i] = (g_score_enc[i] == g_min_bits) ? 0.0f : 1.0f;
    }
}

extern "C" void kernel_launch(void* const* d_in, const int* in_sizes, int n_in,
                              void* d_out, int out_size) {
    const float* h   = (const float*)d_in[0];
    const int*   src = (const int*)d_in[1];   // JAX w/o x64: randint -> int32
    const int*   dst = (const int*)d_in[2];
    float* out = (float*)d_out;

    const int E = in_sizes[1];  // number of edges

    init_kernel<<<1, 1>>>();

    // 256 threads (8 warps) per block; 4 blocks/SM * 148 SMs = one full wave
    // at 32 warps/SM. Grid-stride: each warp handles ~E/4736 edges.
    const int threads = 256;
    const int grid = 148 * 4;
    score_kernel<<<grid, threads>>>(h, src, dst, E);

    finalize_kernel<<<(E + 255) / 256, 256>>>(out, E);
}

// round 3
// speedup vs baseline: 1.9877x; 1.9877x over previous
#include <cuda_runtime.h>
#include <cuda_fp16.h>
#include <cuda_fp8.h>

#define N_NODES 100000
#define D_FEAT  128
#define MAX_E   600000
#define NB2     592      // score kernel grid (one full wave: 148 SMs x 4 CTAs)
#define TPB     256
#define MAXC    8192
#define MARGIN  12.0f    // >> worst-case fp8 coarse-score error (~3)

// Scratch (static __device__ — no allocation allowed)
__device__ unsigned g_h8[N_NODES * D_FEAT / 4];   // h in e4m3, packed 4/uint (12.8 MB)
__device__ float    g_score[MAX_E];               // coarse per-edge scores (2.4 MB)
__device__ float    g_blockmin[NB2];
__device__ int      g_cand[MAXC];
__device__ float    g_cand_score[MAXC];
__device__ int      g_ncand;

__device__ __forceinline__ __half2 fp8x2_to_h2(unsigned short v) {
    __half2_raw r = __nv_cvt_fp8x2_to_halfraw2((__nv_fp8x2_storage_t)v, __NV_E4M3);
    return *reinterpret_cast<__half2*>(&r);
}

// K1: f32 -> e4m3 conversion of h; also resets candidate counter.
__global__ void convert_kernel(const float* __restrict__ h, int n4) {
    if (blockIdx.x == 0 && threadIdx.x == 0) g_ncand = 0;
    const float4* __restrict__ h4 = (const float4*)h;
    const int stride = gridDim.x * blockDim.x;
    for (int i = blockIdx.x * blockDim.x + threadIdx.x; i < n4; i += stride) {
        float4 f = h4[i];
        unsigned lo = __nv_cvt_float2_to_fp8x2(make_float2(f.x, f.y), __NV_SATFINITE, __NV_E4M3);
        unsigned hi = __nv_cvt_float2_to_fp8x2(make_float2(f.z, f.w), __NV_SATFINITE, __NV_E4M3);
        g_h8[i] = lo | (hi << 16);
    }
}

// K2: coarse per-edge dot from fp8 rows. 8-lane group per edge; each lane
// loads one uint4 (16 fp8) of each row -> half2 FMA -> fp32 cross-lane reduce.
__global__ void score_kernel(const int* __restrict__ src,
                             const int* __restrict__ dst, int E) {
    const int lane = threadIdx.x & 31;
    const int gl   = lane & 7;
    const int gid  = (blockIdx.x * blockDim.x + threadIdx.x) >> 3;
    const int nG   = (gridDim.x * blockDim.x) >> 3;
    const uint4* __restrict__ h8 = (const uint4*)g_h8;   // row = 8 x uint4 = 128B

    float lmin = 3.4e38f;

    for (int e = gid; e < E; e += nG) {
        const int s = src[e];
        const int d = dst[e];
        uint4 ua = h8[(long long)s * 8 + gl];
        uint4 ub = h8[(long long)d * 8 + gl];
        __half2 acc = __float2half2_rn(0.f);
        const unsigned* pa = &ua.x;
        const unsigned* pb = &ub.x;
        #pragma unroll
        for (int j = 0; j < 4; j++) {
            unsigned a = pa[j], b = pb[j];
            acc = __hfma2(fp8x2_to_h2((unsigned short)(a & 0xFFFFu)),
                          fp8x2_to_h2((unsigned short)(b & 0xFFFFu)), acc);
            acc = __hfma2(fp8x2_to_h2((unsigned short)(a >> 16)),
                          fp8x2_to_h2((unsigned short)(b >> 16)), acc);
        }
        float facc = __low2float(acc) + __high2float(acc);
        #pragma unroll
        for (int off = 4; off; off >>= 1)
            facc += __shfl_xor_sync(0xFFFFFFFFu, facc, off);
        if (gl == 0) g_score[e] = facc;
        lmin = fminf(lmin, facc);
    }

    // Block min -> array (no atomics, no init kernel needed)
    __shared__ float sm[TPB / 32];
    #pragma unroll
    for (int off = 16; off; off >>= 1)
        lmin = fminf(lmin, __shfl_xor_sync(0xFFFFFFFFu, lmin, off));
    if (lane == 0) sm[threadIdx.x >> 5] = lmin;
    __syncthreads();
    if (threadIdx.x == 0) {
        float m = sm[0];
        #pragma unroll
        for (int i = 1; i < TPB / 32; i++) m = fminf(m, sm[i]);
        g_blockmin[blockIdx.x] = m;
    }
}

// K3: reduce block minima (same order in every block -> identical gmin),
// write 1.0 everywhere, collect candidates within MARGIN of coarse min.
__global__ void threshold_kernel(float* __restrict__ out, int E) {
    __shared__ float sm[TPB / 32];
    float m = 3.4e38f;
    for (int i = threadIdx.x; i < NB2; i += blockDim.x)
        m = fminf(m, g_blockmin[i]);
    #pragma unroll
    for (int off = 16; off; off >>= 1)
        m = fminf(m, __shfl_xor_sync(0xFFFFFFFFu, m, off));
    if ((threadIdx.x & 31) == 0) sm[threadIdx.x >> 5] = m;
    __syncthreads();
    float gmin = sm[0];
    #pragma unroll
    for (int i = 1; i < TPB / 32; i++) gmin = fminf(gmin, sm[i]);

    const int e = blockIdx.x * blockDim.x + threadIdx.x;
    if (e < E) {
        float sc = g_score[e];
        out[e] = 1.0f;
        if (sc <= gmin + MARGIN) {
            int idx = atomicAdd(&g_ncand, 1);
            if (idx < MAXC) g_cand[idx] = e;
        }
    }
}

// K4: exact fp32 rescore of the few candidates; mark the true min edge(s).
__global__ void refine_kernel(const float* __restrict__ h,
                              const int* __restrict__ src,
                              const int* __restrict__ dst,
                              float* __restrict__ out) {
    __shared__ float sm[TPB / 32];
    const int nc = min(g_ncand, MAXC);
    float lmin = 3.4e38f;
    for (int i = threadIdx.x; i < nc; i += blockDim.x) {
        const int e = g_cand[i];
        const float4* a = (const float4*)(h + (long long)src[e] * D_FEAT);
        const float4* b = (const float4*)(h + (long long)dst[e] * D_FEAT);
        float acc = 0.f;
        #pragma unroll
        for (int k = 0; k < D_FEAT / 4; k++) {
            float4 x = a[k], y = b[k];
            acc += x.x * y.x + x.y * y.y + x.z * y.z + x.w * y.w;
        }
        g_cand_score[i] = acc;
        lmin = fminf(lmin, acc);
    }
    #pragma unroll
    for (int off = 16; off; off >>= 1)
        lmin = fminf(lmin, __shfl_xor_sync(0xFFFFFFFFu, lmin, off));
    if ((threadIdx.x & 31) == 0) sm[threadIdx.x >> 5] = lmin;
    __syncthreads();
    float gm = sm[0];
    #pragma unroll
    for (int i = 1; i < TPB / 32; i++) gm = fminf(gm, sm[i]);

    for (int i = threadIdx.x; i < nc; i += blockDim.x)
        if (g_cand_score[i] == gm) out[g_cand[i]] = 0.0f;
}

extern "C" void kernel_launch(void* const* d_in, const int* in_sizes, int n_in,
                              void* d_out, int out_size) {
    const float* h   = (const float*)d_in[0];
    const int*   src = (const int*)d_in[1];
    const int*   dst = (const int*)d_in[2];
    float* out = (float*)d_out;

    const int E  = in_sizes[1];
    const int n4 = N_NODES * D_FEAT / 4;

    convert_kernel<<<NB2, TPB>>>(h, n4);
    score_kernel<<<NB2, TPB>>>(src, dst, E);
    threshold_kernel<<<(E + TPB - 1) / TPB, TPB>>>(out, E);
    refine_kernel<<<1, TPB>>>(h, src, dst, out);
}